// round 3
// baseline (speedup 1.0000x reference)
#include <cuda_runtime.h>
#include <math.h>
#include <stdint.h>

#define N 512
#define N2 (N*N)
#define BATCH 128
#define NMAT 129           // 128 batch matrices + 1 for L0
#define NBP 64             // panel width
#define NPANEL (N/NBP)
#define EPSF 1e-7f
#define NTHR 512

typedef unsigned long long u64;

// packed f32x2 ops (Blackwell FFMA2 — only reachable via PTX)
__device__ __forceinline__ u64 ffma2(u64 a, u64 b, u64 c) {
    u64 d;
    asm("fma.rn.f32x2 %0, %1, %2, %3;" : "=l"(d) : "l"(a), "l"(b), "l"(c));
    return d;
}
__device__ __forceinline__ u64 fadd2(u64 a, u64 b) {
    u64 d;
    asm("add.rn.f32x2 %0, %1, %2;" : "=l"(d) : "l"(a), "l"(b));
    return d;
}
__device__ __forceinline__ u64 pack_dup(float a) {
    u64 d; unsigned int u = __float_as_uint(a);
    asm("mov.b64 %0, {%1, %1};" : "=l"(d) : "r"(u));
    return d;
}
__device__ __forceinline__ u64 pack2(float lo, float hi) {
    u64 d;
    asm("mov.b64 %0, {%1, %2};" : "=l"(d) : "f"(lo), "f"(hi));
    return d;
}
__device__ __forceinline__ void unpack2(u64 v, float& lo, float& hi) {
    asm("mov.b64 {%0, %1}, %2;" : "=f"(lo), "=f"(hi) : "l"(v));
}

// ---------------- device scratch (no allocations allowed) ----------------
__device__ float g_C[4 * N2];                                   // 4 planes, 4 MB
__device__ __align__(16) float g_M[(size_t)NMAT * N2 + 64];     // 129 matrices
__device__ float g_logdet[NMAT];

// ---------------- kernel 1: IPF + plane construction ----------------
__global__ void k_ipf(const float* __restrict__ W, const float* __restrict__ Vc,
                      const float* __restrict__ Ec) {
    int p = blockIdx.x * blockDim.x + threadIdx.x;
    int i = p >> 9;
    int j = p & (N - 1);

    float4 e4 = reinterpret_cast<const float4*>(Ec)[p];
    float e00 = expf(e4.x), e01 = expf(e4.y), e10 = expf(e4.z), e11 = expf(e4.w);
    float inv = 1.0f / (e00 + e01 + e10 + e11);
    e00 *= inv; e01 *= inv; e10 *= inv; e11 *= inv;

    float a0 = Vc[2*i], a1 = Vc[2*i+1];
    float mi = fmaxf(a0, a1);
    float xa0 = expf(a0 - mi), xa1 = expf(a1 - mi);
    float di = 1.0f / (xa0 + xa1);
    float vi0 = xa0 * di, vi1 = xa1 * di;

    float b0 = Vc[2*j], b1 = Vc[2*j+1];
    float mj = fmaxf(b0, b1);
    float xb0 = expf(b0 - mj), xb1 = expf(b1 - mj);
    float dj = 1.0f / (xb0 + xb1);
    float vj0 = xb0 * dj, vj1 = xb1 * dj;

    #pragma unroll
    for (int it = 0; it < 10; it++) {
        float r0 = e00 + e01 + EPSF, r1 = e10 + e11 + EPSF;
        float c0 = e00 + e10 + EPSF, c1 = e01 + e11 + EPSF;
        float f0 = vi0 / r0, f1 = vi1 / r1;
        e00 *= f0; e01 *= f0; e10 *= f1; e11 *= f1;
        float g0 = vj0 / c0, g1 = vj1 / c1;
        e00 *= g0; e10 *= g0; e01 *= g1; e11 *= g1;
        float iv = 1.0f / (e00 + e01 + e10 + e11 + EPSF);
        e00 *= iv; e01 *= iv; e10 *= iv; e11 *= iv;
    }

    float wm = 0.0f;
    if (i != j) {
        float w = (i > j) ? W[i*N + j] : W[j*N + i];
        wm = 1.0f / (1.0f + expf(-w));
    } else {
        e00 = e01 = e10 = e11 = 0.0f;
    }
    e00 = fminf(fmaxf(e00, 0.0f), 1.0f);
    e01 = fminf(fmaxf(e01, 0.0f), 1.0f);
    e10 = fminf(fmaxf(e10, 0.0f), 1.0f);
    e11 = fminf(fmaxf(e11, 0.0f), 1.0f);

    g_C[0*N2 + p] = wm * e00 / (vi0 * vj0);
    g_C[1*N2 + p] = wm * e01 / (vi0 * vj1);
    g_C[2*N2 + p] = wm * e10 / (vi1 * vj0);
    g_C[3*N2 + p] = wm * e11 / (vi1 * vj1);
}

// ---------------- kernel 2: build matrix + blocked LU (NB=64, no pivoting) ----------------
#define SP_ST 68              // panel stride: rows 16B-aligned (68*4=272), no 8-row bank alias
#define SU_ST 264             // U12 block stride (264*4 = 16B multiple)
#define SMEM_LU_BYTES ((N*SP_ST + NBP*SU_ST) * 4 + N * 4 + 64)

__global__ void __launch_bounds__(NTHR, 1) k_lu(const int* __restrict__ x,
                                                const float* __restrict__ W) {
    extern __shared__ float smem[];
    float* sP   = smem;                     // panel [rrel*68 + k], rrel = row - j0
    float* sU   = sP + N * SP_ST;           // NEGATED U12 block [k*264 + crel]
    int*   sx   = (int*)(sU + NBP * SU_ST);
    float* sacc = (float*)(sx + N);

    const int batch = blockIdx.x;
    const int tid   = threadIdx.x;
    float* Mb = g_M + (size_t)batch * N2;

    if (batch < BATCH) {
        for (int t = tid; t < N; t += NTHR) sx[t] = x[batch*N + t];
    }
    if (tid == 0) sacc[0] = 0.0f;
    __syncthreads();

    // ---- build padded 512x512 matrix (rows 0..510 <-> nodes 1..511) ----
    {
        int w = tid >> 5, lane = tid & 31;
        for (int r = w; r < N; r += 16) {
            if (r == N - 1) {
                for (int c = lane; c < N; c += 32) Mb[r*N + c] = (c == N-1) ? 1.0f : 0.0f;
                continue;
            }
            int i = r + 1;
            float sum = 0.0f;
            if (batch < BATCH) {
                int xi = sx[i];
                const float* p0 = g_C + (size_t)(xi*2) * N2 + (size_t)i * N;
                const float* p1 = p0 + N2;
                for (int j = lane; j < N; j += 32) {
                    float v0 = p0[j], v1 = p1[j];
                    float v = sx[j] ? v1 : v0;
                    sum += v;
                    int c = j - 1;
                    if (j > 0 && c != r) Mb[r*N + c] = -v;
                }
            } else {
                for (int j = lane; j < N; j += 32) {
                    float v = 0.0f;
                    if (j != i) {
                        float wv = (i > j) ? W[i*N + j] : W[j*N + i];
                        v = 1.0f / (1.0f + expf(-wv));
                    }
                    sum += v;
                    int c = j - 1;
                    if (j > 0 && c != r) Mb[r*N + c] = -v;
                }
            }
            #pragma unroll
            for (int off = 16; off; off >>= 1) sum += __shfl_xor_sync(0xffffffffu, sum, off);
            if (lane == 0) { Mb[r*N + r] = sum; Mb[r*N + (N-1)] = 0.0f; }
        }
    }
    __syncthreads();

    const int tx = tid & 15, ty = tid >> 4;

    // ---- blocked LU, NB=64 ----
    for (int kb = 0; kb < NPANEL; kb++) {
        const int j0 = kb * NBP, j1 = j0 + NBP;
        const int mP = N - j0;              // panel rows
        const int m  = N - j1;              // trailing size

        // load panel [rows j0..511, cols j0..j0+63] into sP (relative rows)
        for (int e = tid; e < mP * NBP; e += NTHR) {
            int rr = e >> 6, k = e & 63;
            sP[rr*SP_ST + k] = Mb[(j0+rr)*N + j0 + k];
        }
        __syncthreads();

        // factor panel in-place (unpivoted; diag-dominant Laplacian => pivots > 0)
        for (int j = 0; j < NBP; j++) {
            float pinv = 1.0f / sP[j*SP_ST + j];
            int idx = j + 1 + tid;
            if (idx < mP) {
                float l = sP[idx*SP_ST + j] * pinv;
                sP[idx*SP_ST + j] = l;
                u64 nl2 = pack_dup(-l);
                int k = j + 1;
                for (; k < NBP && (k & 3); k++)
                    sP[idx*SP_ST + k] -= l * sP[j*SP_ST + k];
                for (; k < NBP; k += 4) {
                    ulonglong2 piv = *reinterpret_cast<const ulonglong2*>(&sP[j*SP_ST + k]);
                    ulonglong2 own = *reinterpret_cast<ulonglong2*>(&sP[idx*SP_ST + k]);
                    own.x = ffma2(nl2, piv.x, own.x);
                    own.y = ffma2(nl2, piv.y, own.y);
                    *reinterpret_cast<ulonglong2*>(&sP[idx*SP_ST + k]) = own;
                }
            }
            __syncthreads();
        }

        // logdet from the 64 diagonal pivots
        if (tid < 32) {
            float v = logf(fabsf(sP[tid*SP_ST + tid]))
                    + logf(fabsf(sP[(tid+32)*SP_ST + tid + 32]));
            #pragma unroll
            for (int off = 16; off; off >>= 1) v += __shfl_xor_sync(0xffffffffu, v, off);
            if (tid == 0) sacc[0] += v;
        }

        if (m > 0) {
            for (int cb = j1; cb < N; cb += 256) {
                int cw = min(256, N - cb);

                // trisolve: sU = -(L11^{-1} A12) for this column block
                if (tid < cw) {
                    int c = cb + tid;
                    float y[NBP];
                    #pragma unroll
                    for (int k = 0; k < NBP; k++) y[k] = Mb[(j0+k)*N + c];

                    u64 yn2[NBP/2];
                    yn2[0] = pack2(-y[0], -(y[1] -= sP[1*SP_ST + 0] * y[0]));
                    #pragma unroll
                    for (int j = 2; j < NBP; j++) {
                        u64 acc2 = 0;
                        const int q = j >> 1;       // # finished pairs
                        #pragma unroll
                        for (int t2 = 0; t2 + 2 <= q; t2 += 2) {
                            ulonglong2 L2 = *reinterpret_cast<const ulonglong2*>(
                                &sP[j*SP_ST + 2*t2]);
                            acc2 = ffma2(L2.x, yn2[t2], acc2);
                            acc2 = ffma2(L2.y, yn2[t2+1], acc2);
                        }
                        if (q & 1) {
                            u64 Lp = *reinterpret_cast<const u64*>(&sP[j*SP_ST + 2*(q-1)]);
                            acc2 = ffma2(Lp, yn2[q-1], acc2);
                        }
                        float lo, hi; unpack2(acc2, lo, hi);
                        float acc = y[j] + lo + hi;
                        if (j & 1) {                 // odd j: scalar tail t = j-1
                            acc -= sP[j*SP_ST + (j-1)] * y[j-1];
                            y[j] = acc;
                            yn2[j>>1] = pack2(-y[j-1], -acc);
                        } else {
                            y[j] = acc;
                        }
                    }
                    #pragma unroll
                    for (int k = 0; k < NBP; k++) sU[k*SU_ST + tid] = -y[k];
                }
                __syncthreads();

                // trailing update: A22 += L21 * (-U12); 8x8/thread, rows strided by 32
                for (int cc = 0; cc < cw; cc += 128) {
                    int cwc = min(128, cw - cc);
                    int crel = cc + tx*8;
                    if (tx*8 < cwc) {
                        int c0 = cb + crel;
                        for (int rb = j1; rb < N; rb += 256) {
                            bool rok[8]; int rg[8], rp[8];
                            #pragma unroll
                            for (int ii = 0; ii < 8; ii++) {
                                int r = rb + ty + 32*ii;
                                rok[ii] = (r < N);
                                rg[ii]  = rok[ii] ? r : (N-1);
                                rp[ii]  = rok[ii] ? (r - j0) : 0;
                            }
                            // prefetch original A22 values (consumed after k-loop)
                            ulonglong2 pfA[8], pfB[8];
                            #pragma unroll
                            for (int ii = 0; ii < 8; ii++) {
                                const ulonglong2* src =
                                    reinterpret_cast<const ulonglong2*>(&Mb[(size_t)rg[ii]*N + c0]);
                                pfA[ii] = src[0];
                                pfB[ii] = src[1];
                            }
                            u64 acc[8][4];
                            #pragma unroll
                            for (int ii = 0; ii < 8; ii++)
                                acc[ii][0] = acc[ii][1] = acc[ii][2] = acc[ii][3] = 0;

                            #pragma unroll 8
                            for (int k = 0; k < NBP; k++) {
                                ulonglong2 b0 = *reinterpret_cast<const ulonglong2*>(
                                    &sU[k*SU_ST + crel]);
                                ulonglong2 b1 = *reinterpret_cast<const ulonglong2*>(
                                    &sU[k*SU_ST + crel + 4]);
                                #pragma unroll
                                for (int ii = 0; ii < 8; ii++) {
                                    u64 a2 = pack_dup(sP[rp[ii]*SP_ST + k]);
                                    acc[ii][0] = ffma2(a2, b0.x, acc[ii][0]);
                                    acc[ii][1] = ffma2(a2, b0.y, acc[ii][1]);
                                    acc[ii][2] = ffma2(a2, b1.x, acc[ii][2]);
                                    acc[ii][3] = ffma2(a2, b1.y, acc[ii][3]);
                                }
                            }
                            #pragma unroll
                            for (int ii = 0; ii < 8; ii++) {
                                if (rok[ii]) {
                                    ulonglong2 o0, o1;
                                    o0.x = fadd2(acc[ii][0], pfA[ii].x);
                                    o0.y = fadd2(acc[ii][1], pfA[ii].y);
                                    o1.x = fadd2(acc[ii][2], pfB[ii].x);
                                    o1.y = fadd2(acc[ii][3], pfB[ii].y);
                                    ulonglong2* dst =
                                        reinterpret_cast<ulonglong2*>(&Mb[(size_t)rg[ii]*N + c0]);
                                    dst[0] = o0;
                                    dst[1] = o1;
                                }
                            }
                        }
                    }
                }
                __syncthreads();
            }
        }
        __syncthreads();   // protect sP (and sacc path) before next panel load
    }
    if (tid == 0) g_logdet[batch] = sacc[0];
}

// ---------------- kernel 3: combine ----------------
__global__ void k_final(const int* __restrict__ x, const float* __restrict__ Vc,
                        float* __restrict__ out) {
    __shared__ float red[256];
    int b = blockIdx.x, tid = threadIdx.x;
    float s = 0.0f;
    for (int i = tid; i < N; i += 256) {
        int xi = x[b*N + i];
        float a0 = Vc[2*i], a1 = Vc[2*i+1];
        float m = fmaxf(a0, a1);
        float lse = m + logf(expf(a0 - m) + expf(a1 - m));
        s += (xi ? a1 : a0) - lse;
    }
    red[tid] = s;
    __syncthreads();
    #pragma unroll
    for (int o = 128; o; o >>= 1) {
        if (tid < o) red[tid] += red[tid + o];
        __syncthreads();
    }
    if (tid == 0) out[b] = red[0] + g_logdet[b] - g_logdet[BATCH];
}

// ---------------- launcher ----------------
extern "C" void kernel_launch(void* const* d_in, const int* in_sizes, int n_in,
                              void* d_out, int out_size) {
    const int* x = nullptr;
    const float* W = nullptr;
    const float* Vc = nullptr;
    const float* Ec = nullptr;
    for (int k = 0; k < n_in; k++) {
        switch (in_sizes[k]) {
            case BATCH * N:   x  = (const int*)d_in[k];   break;  // 65536
            case N * N:       W  = (const float*)d_in[k]; break;  // 262144
            case N * 2:       Vc = (const float*)d_in[k]; break;  // 1024
            case N * N * 4:   Ec = (const float*)d_in[k]; break;  // 1048576
        }
    }
    float* out = (float*)d_out;

    cudaFuncSetAttribute(k_lu, cudaFuncAttributeMaxDynamicSharedMemorySize, SMEM_LU_BYTES);

    k_ipf<<<N2 / 256, 256>>>(W, Vc, Ec);
    k_lu<<<NMAT, NTHR, SMEM_LU_BYTES>>>(x, W);
    k_final<<<BATCH, 256>>>(x, Vc, out);
}

// round 4
// speedup vs baseline: 1.0318x; 1.0318x over previous
#include <cuda_runtime.h>
#include <math.h>
#include <stdint.h>

#define N 512
#define N2 (N*N)
#define BATCH 128
#define NMAT 129           // 128 batch matrices + 1 for L0
#define EPSF 1e-7f
#define NTHR 512
#define NPAIR 8            // 8 pairs of 32-wide panels = rank-64 updates

typedef unsigned long long u64;

// packed f32x2 ops (Blackwell FFMA2 — only reachable via PTX)
__device__ __forceinline__ u64 ffma2(u64 a, u64 b, u64 c) {
    u64 d;
    asm("fma.rn.f32x2 %0, %1, %2, %3;" : "=l"(d) : "l"(a), "l"(b), "l"(c));
    return d;
}
__device__ __forceinline__ u64 fadd2(u64 a, u64 b) {
    u64 d;
    asm("add.rn.f32x2 %0, %1, %2;" : "=l"(d) : "l"(a), "l"(b));
    return d;
}
__device__ __forceinline__ u64 pack_dup(float a) {
    u64 d; unsigned int u = __float_as_uint(a);
    asm("mov.b64 %0, {%1, %1};" : "=l"(d) : "r"(u));
    return d;
}
__device__ __forceinline__ void unpack2(u64 v, float& lo, float& hi) {
    asm("mov.b64 {%0, %1}, %2;" : "=f"(lo), "=f"(hi) : "l"(v));
}

// ---------------- device scratch (no allocations allowed) ----------------
__device__ float g_C[4 * N2];                                   // 4 planes, 4 MB
__device__ __align__(16) float g_M[(size_t)NMAT * N2 + 64];     // 129 matrices
__device__ float g_logdet[NMAT];

// ---------------- kernel 1: IPF + plane construction ----------------
__global__ void k_ipf(const float* __restrict__ W, const float* __restrict__ Vc,
                      const float* __restrict__ Ec) {
    int p = blockIdx.x * blockDim.x + threadIdx.x;
    int i = p >> 9;
    int j = p & (N - 1);

    float4 e4 = reinterpret_cast<const float4*>(Ec)[p];
    float e00 = expf(e4.x), e01 = expf(e4.y), e10 = expf(e4.z), e11 = expf(e4.w);
    float inv = 1.0f / (e00 + e01 + e10 + e11);
    e00 *= inv; e01 *= inv; e10 *= inv; e11 *= inv;

    float a0 = Vc[2*i], a1 = Vc[2*i+1];
    float mi = fmaxf(a0, a1);
    float xa0 = expf(a0 - mi), xa1 = expf(a1 - mi);
    float di = 1.0f / (xa0 + xa1);
    float vi0 = xa0 * di, vi1 = xa1 * di;

    float b0 = Vc[2*j], b1 = Vc[2*j+1];
    float mj = fmaxf(b0, b1);
    float xb0 = expf(b0 - mj), xb1 = expf(b1 - mj);
    float dj = 1.0f / (xb0 + xb1);
    float vj0 = xb0 * dj, vj1 = xb1 * dj;

    #pragma unroll
    for (int it = 0; it < 10; it++) {
        float r0 = e00 + e01 + EPSF, r1 = e10 + e11 + EPSF;
        float c0 = e00 + e10 + EPSF, c1 = e01 + e11 + EPSF;
        float f0 = vi0 / r0, f1 = vi1 / r1;
        e00 *= f0; e01 *= f0; e10 *= f1; e11 *= f1;
        float g0 = vj0 / c0, g1 = vj1 / c1;
        e00 *= g0; e10 *= g0; e01 *= g1; e11 *= g1;
        float iv = 1.0f / (e00 + e01 + e10 + e11 + EPSF);
        e00 *= iv; e01 *= iv; e10 *= iv; e11 *= iv;
    }

    float wm = 0.0f;
    if (i != j) {
        float w = (i > j) ? W[i*N + j] : W[j*N + i];
        wm = 1.0f / (1.0f + expf(-w));
    } else {
        e00 = e01 = e10 = e11 = 0.0f;
    }
    e00 = fminf(fmaxf(e00, 0.0f), 1.0f);
    e01 = fminf(fmaxf(e01, 0.0f), 1.0f);
    e10 = fminf(fmaxf(e10, 0.0f), 1.0f);
    e11 = fminf(fmaxf(e11, 0.0f), 1.0f);

    g_C[0*N2 + p] = wm * e00 / (vi0 * vj0);
    g_C[1*N2 + p] = wm * e01 / (vi0 * vj1);
    g_C[2*N2 + p] = wm * e10 / (vi1 * vj0);
    g_C[3*N2 + p] = wm * e11 / (vi1 * vj1);
}

// ---------------- kernel 2: build + paired-panel LU (rank-64 updates) ----------------
#define SPA_ST 33             // 512 x 33 panel A  (rows rel j0)
#define SPB_ST 33             // 480 x 33 panel B  (rows rel j0+32)
#define SU_ST 264             // 64 x 264 negated-U block (16B-aligned rows)
#define SMEM_LU_BYTES ((N*SPA_ST + 480*SPB_ST + 64*SU_ST) * 4 + N * 4 + 16)

__global__ void __launch_bounds__(NTHR, 1) k_lu(const int* __restrict__ x,
                                                const float* __restrict__ W) {
    extern __shared__ float smem[];
    float* sPA  = smem;                      // [rrel*33 + k], rrel = row - j0
    float* sPB  = sPA + N * SPA_ST;          // [rrel*33 + k], rrel = row - (j0+32)
    float* sU   = sPB + 480 * SPB_ST;        // NEGATED U [k*264 + crel]
    int*   sx   = (int*)(sU + 64 * SU_ST);
    float* sacc = (float*)(sx + N);

    const int batch = blockIdx.x;
    const int tid   = threadIdx.x;
    float* Mb = g_M + (size_t)batch * N2;

    if (batch < BATCH) {
        for (int t = tid; t < N; t += NTHR) sx[t] = x[batch*N + t];
    }
    if (tid == 0) sacc[0] = 0.0f;
    __syncthreads();

    // ---- build padded 512x512 matrix (rows 0..510 <-> nodes 1..511) ----
    {
        int w = tid >> 5, lane = tid & 31;
        for (int r = w; r < N; r += 16) {
            if (r == N - 1) {
                for (int c = lane; c < N; c += 32) Mb[r*N + c] = (c == N-1) ? 1.0f : 0.0f;
                continue;
            }
            int i = r + 1;
            float sum = 0.0f;
            if (batch < BATCH) {
                int xi = sx[i];
                const float* p0 = g_C + (size_t)(xi*2) * N2 + (size_t)i * N;
                const float* p1 = p0 + N2;
                for (int j = lane; j < N; j += 32) {
                    float v0 = p0[j], v1 = p1[j];
                    float v = sx[j] ? v1 : v0;
                    sum += v;
                    int c = j - 1;
                    if (j > 0 && c != r) Mb[r*N + c] = -v;
                }
            } else {
                for (int j = lane; j < N; j += 32) {
                    float v = 0.0f;
                    if (j != i) {
                        float wv = (i > j) ? W[i*N + j] : W[j*N + i];
                        v = 1.0f / (1.0f + expf(-wv));
                    }
                    sum += v;
                    int c = j - 1;
                    if (j > 0 && c != r) Mb[r*N + c] = -v;
                }
            }
            #pragma unroll
            for (int off = 16; off; off >>= 1) sum += __shfl_xor_sync(0xffffffffu, sum, off);
            if (lane == 0) { Mb[r*N + r] = sum; Mb[r*N + (N-1)] = 0.0f; }
        }
    }
    __syncthreads();

    const int tx = tid & 15, ty = tid >> 4;

    for (int pair = 0; pair < NPAIR; pair++) {
        const int j0 = pair * 64, jB = j0 + 32, j1 = j0 + 64;
        const int mA = N - j0;       // panel A rows
        const int mB = N - jB;       // panel B rows
        const int m2 = N - j1;       // trailing size

        // ---- load + factor panel A (cols j0..j0+31, rows j0..511) ----
        for (int e = tid; e < mA * 32; e += NTHR) {
            int rr = e >> 5, k = e & 31;
            sPA[rr*SPA_ST + k] = Mb[(size_t)(j0+rr)*N + j0 + k];
        }
        __syncthreads();
        for (int j = 0; j < 32; j++) {
            float pinv = 1.0f / sPA[j*SPA_ST + j];
            int idx = j + 1 + tid;
            if (idx < mA) {
                float l = sPA[idx*SPA_ST + j] * pinv;
                sPA[idx*SPA_ST + j] = l;
                #pragma unroll
                for (int c = j + 1; c < 32; c++)
                    sPA[idx*SPA_ST + c] -= l * sPA[j*SPA_ST + c];
            }
            __syncthreads();
        }

        // ---- U_A for panel-B columns -> sU rows 0..31, cols 0..31 (negated) ----
        if (tid < 32) {
            int c = jB + tid;
            float y[32];
            #pragma unroll
            for (int k = 0; k < 32; k++) y[k] = Mb[(size_t)(j0+k)*N + c];
            #pragma unroll
            for (int k = 1; k < 32; k++) {
                float acc = y[k];
                #pragma unroll
                for (int t = 0; t < k; t++) acc -= sPA[k*SPA_ST + t] * y[t];
                y[k] = acc;
            }
            #pragma unroll
            for (int k = 0; k < 32; k++) sU[k*SU_ST + tid] = -y[k];
        }
        __syncthreads();

        // ---- B strip: load + rank-32 update into sPB (rows jB..511) ----
        {
            int r = tid;
            if (r < mB) {
                const ulonglong2* src =
                    reinterpret_cast<const ulonglong2*>(&Mb[(size_t)(jB+r)*N + jB]);
                u64 acc[16];
                #pragma unroll
                for (int q = 0; q < 8; q++) {
                    ulonglong2 v = src[q];
                    acc[2*q] = v.x; acc[2*q+1] = v.y;
                }
                #pragma unroll 4
                for (int k = 0; k < 32; k++) {
                    u64 a2 = pack_dup(sPA[(r+32)*SPA_ST + k]);
                    const u64* bro = reinterpret_cast<const u64*>(&sU[k*SU_ST]);
                    #pragma unroll
                    for (int q = 0; q < 16; q++)
                        acc[q] = ffma2(a2, bro[q], acc[q]);
                }
                #pragma unroll
                for (int q = 0; q < 16; q++) {
                    float lo, hi; unpack2(acc[q], lo, hi);
                    sPB[r*SPB_ST + 2*q] = lo;
                    sPB[r*SPB_ST + 2*q + 1] = hi;
                }
            }
        }
        __syncthreads();

        // ---- factor panel B in sPB ----
        for (int j = 0; j < 32; j++) {
            float pinv = 1.0f / sPB[j*SPB_ST + j];
            int idx = j + 1 + tid;
            if (idx < mB) {
                float l = sPB[idx*SPB_ST + j] * pinv;
                sPB[idx*SPB_ST + j] = l;
                #pragma unroll
                for (int c = j + 1; c < 32; c++)
                    sPB[idx*SPB_ST + c] -= l * sPB[j*SPB_ST + c];
            }
            __syncthreads();
        }

        // ---- logdet from the 64 pivots ----
        if (tid < 32) {
            float v = logf(fabsf(sPA[tid*SPA_ST + tid]))
                    + logf(fabsf(sPB[tid*SPB_ST + tid]));
            #pragma unroll
            for (int off = 16; off; off >>= 1) v += __shfl_xor_sync(0xffffffffu, v, off);
            if (tid == 0) sacc[0] += v;
        }

        // ---- trailing: rank-64 update, 256-col chunks ----
        for (int cb = j1; cb < N; cb += 256) {
            int cw = min(256, N - cb);          // always a multiple of 64

            // trisolve 64-deep: sU = -(L^{-1} A12) for this chunk
            if (tid < cw) {
                int c = cb + tid;
                float y[64];
                #pragma unroll
                for (int k = 0; k < 64; k++) y[k] = Mb[(size_t)(j0+k)*N + c];
                #pragma unroll
                for (int k = 1; k < 32; k++) {
                    float acc = y[k];
                    #pragma unroll
                    for (int t = 0; t < k; t++) acc -= sPA[k*SPA_ST + t] * y[t];
                    y[k] = acc;
                }
                #pragma unroll
                for (int k = 32; k < 64; k++) {
                    float acc = y[k];
                    #pragma unroll
                    for (int t = 0; t < 32; t++) acc -= sPA[k*SPA_ST + t] * y[t];
                    #pragma unroll
                    for (int t = 32; t < k; t++)
                        acc -= sPB[(k-32)*SPB_ST + (t-32)] * y[t];
                    y[k] = acc;
                }
                #pragma unroll
                for (int k = 0; k < 64; k++) sU[k*SU_ST + tid] = -y[k];
            }
            __syncthreads();

            // GEMM: A22 += L * (-U); 8 rows x (4+4) cols per thread
            for (int cc = 0; cc < cw; cc += 128) {
                const bool gb = (cc + 128 <= cw);       // second 64-col group valid?
                const int c0a = cb + cc + tx*4;
                const int c0b = c0a + 64;
                for (int rb = j1; rb < N; rb += 256) {
                    bool rok[8]; int rpA[8], rpB[8], rg[8];
                    #pragma unroll
                    for (int ii = 0; ii < 8; ii++) {
                        int r = rb + ty + 32*ii;
                        rok[ii] = (r < N);
                        rg[ii]  = rok[ii] ? r : (N-1);
                        rpA[ii] = rg[ii] - j0;
                        rpB[ii] = rg[ii] - jB;
                    }
                    u64 acc[8][4];
                    #pragma unroll
                    for (int ii = 0; ii < 8; ii++)
                        acc[ii][0] = acc[ii][1] = acc[ii][2] = acc[ii][3] = 0;

                    #pragma unroll 8
                    for (int k = 0; k < 32; k++) {
                        ulonglong2 bA = *reinterpret_cast<const ulonglong2*>(
                            &sU[k*SU_ST + cc + tx*4]);
                        ulonglong2 bB = *reinterpret_cast<const ulonglong2*>(
                            &sU[k*SU_ST + cc + 64 + tx*4]);
                        #pragma unroll
                        for (int ii = 0; ii < 8; ii++) {
                            u64 a2 = pack_dup(sPA[rpA[ii]*SPA_ST + k]);
                            acc[ii][0] = ffma2(a2, bA.x, acc[ii][0]);
                            acc[ii][1] = ffma2(a2, bA.y, acc[ii][1]);
                            acc[ii][2] = ffma2(a2, bB.x, acc[ii][2]);
                            acc[ii][3] = ffma2(a2, bB.y, acc[ii][3]);
                        }
                    }
                    #pragma unroll 8
                    for (int k = 32; k < 64; k++) {
                        ulonglong2 bA = *reinterpret_cast<const ulonglong2*>(
                            &sU[k*SU_ST + cc + tx*4]);
                        ulonglong2 bB = *reinterpret_cast<const ulonglong2*>(
                            &sU[k*SU_ST + cc + 64 + tx*4]);
                        #pragma unroll
                        for (int ii = 0; ii < 8; ii++) {
                            u64 a2 = pack_dup(sPB[rpB[ii]*SPB_ST + (k-32)]);
                            acc[ii][0] = ffma2(a2, bA.x, acc[ii][0]);
                            acc[ii][1] = ffma2(a2, bA.y, acc[ii][1]);
                            acc[ii][2] = ffma2(a2, bB.x, acc[ii][2]);
                            acc[ii][3] = ffma2(a2, bB.y, acc[ii][3]);
                        }
                    }
                    // RMW epilogue
                    #pragma unroll
                    for (int ii = 0; ii < 8; ii++) {
                        if (rok[ii]) {
                            ulonglong2* pa =
                                reinterpret_cast<ulonglong2*>(&Mb[(size_t)rg[ii]*N + c0a]);
                            ulonglong2 va = *pa;
                            va.x = fadd2(acc[ii][0], va.x);
                            va.y = fadd2(acc[ii][1], va.y);
                            *pa = va;
                            if (gb) {
                                ulonglong2* pb =
                                    reinterpret_cast<ulonglong2*>(&Mb[(size_t)rg[ii]*N + c0b]);
                                ulonglong2 vb = *pb;
                                vb.x = fadd2(acc[ii][2], vb.x);
                                vb.y = fadd2(acc[ii][3], vb.y);
                                *pb = vb;
                            }
                        }
                    }
                }
            }
            __syncthreads();
        }
    }
    __syncthreads();
    if (tid == 0) g_logdet[batch] = sacc[0];
}

// ---------------- kernel 3: combine ----------------
__global__ void k_final(const int* __restrict__ x, const float* __restrict__ Vc,
                        float* __restrict__ out) {
    __shared__ float red[256];
    int b = blockIdx.x, tid = threadIdx.x;
    float s = 0.0f;
    for (int i = tid; i < N; i += 256) {
        int xi = x[b*N + i];
        float a0 = Vc[2*i], a1 = Vc[2*i+1];
        float m = fmaxf(a0, a1);
        float lse = m + logf(expf(a0 - m) + expf(a1 - m));
        s += (xi ? a1 : a0) - lse;
    }
    red[tid] = s;
    __syncthreads();
    #pragma unroll
    for (int o = 128; o; o >>= 1) {
        if (tid < o) red[tid] += red[tid + o];
        __syncthreads();
    }
    if (tid == 0) out[b] = red[0] + g_logdet[b] - g_logdet[BATCH];
}

// ---------------- launcher ----------------
extern "C" void kernel_launch(void* const* d_in, const int* in_sizes, int n_in,
                              void* d_out, int out_size) {
    const int* x = nullptr;
    const float* W = nullptr;
    const float* Vc = nullptr;
    const float* Ec = nullptr;
    for (int k = 0; k < n_in; k++) {
        switch (in_sizes[k]) {
            case BATCH * N:   x  = (const int*)d_in[k];   break;  // 65536
            case N * N:       W  = (const float*)d_in[k]; break;  // 262144
            case N * 2:       Vc = (const float*)d_in[k]; break;  // 1024
            case N * N * 4:   Ec = (const float*)d_in[k]; break;  // 1048576
        }
    }
    float* out = (float*)d_out;

    cudaFuncSetAttribute(k_lu, cudaFuncAttributeMaxDynamicSharedMemorySize, SMEM_LU_BYTES);

    k_ipf<<<N2 / 256, 256>>>(W, Vc, Ec);
    k_lu<<<NMAT, NTHR, SMEM_LU_BYTES>>>(x, W);
    k_final<<<BATCH, 256>>>(x, Vc, out);
}

// round 5
// speedup vs baseline: 1.0877x; 1.0542x over previous
#include <cuda_runtime.h>
#include <math.h>
#include <stdint.h>

#define N 512
#define N2 (N*N)
#define BATCH 128
#define NMAT 129           // 128 batch matrices + 1 for L0
#define EPSF 1e-7f
#define NTHR 512
#define NPAIR 8            // 8 pairs of 32-wide panels = rank-64 updates

typedef unsigned long long u64;

// packed f32x2 ops (Blackwell FFMA2 — only reachable via PTX)
__device__ __forceinline__ u64 ffma2(u64 a, u64 b, u64 c) {
    u64 d;
    asm("fma.rn.f32x2 %0, %1, %2, %3;" : "=l"(d) : "l"(a), "l"(b), "l"(c));
    return d;
}
__device__ __forceinline__ u64 pack_dup(float a) {
    u64 d; unsigned int u = __float_as_uint(a);
    asm("mov.b64 %0, {%1, %1};" : "=l"(d) : "r"(u));
    return d;
}
__device__ __forceinline__ void unpack2(u64 v, float& lo, float& hi) {
    asm("mov.b64 {%0, %1}, %2;" : "=f"(lo), "=f"(hi) : "l"(v));
}

// ---------------- device scratch (no allocations allowed) ----------------
__device__ float g_C[4 * N2];                                   // 4 planes, 4 MB
__device__ __align__(16) float g_M[(size_t)NMAT * N2 + 64];     // 129 matrices
__device__ float g_logdet[NMAT];

// ---------------- kernel 1: IPF + plane construction ----------------
__global__ void k_ipf(const float* __restrict__ W, const float* __restrict__ Vc,
                      const float* __restrict__ Ec) {
    int p = blockIdx.x * blockDim.x + threadIdx.x;
    int i = p >> 9;
    int j = p & (N - 1);

    float4 e4 = reinterpret_cast<const float4*>(Ec)[p];
    float e00 = expf(e4.x), e01 = expf(e4.y), e10 = expf(e4.z), e11 = expf(e4.w);
    float inv = 1.0f / (e00 + e01 + e10 + e11);
    e00 *= inv; e01 *= inv; e10 *= inv; e11 *= inv;

    float a0 = Vc[2*i], a1 = Vc[2*i+1];
    float mi = fmaxf(a0, a1);
    float xa0 = expf(a0 - mi), xa1 = expf(a1 - mi);
    float di = 1.0f / (xa0 + xa1);
    float vi0 = xa0 * di, vi1 = xa1 * di;

    float b0 = Vc[2*j], b1 = Vc[2*j+1];
    float mj = fmaxf(b0, b1);
    float xb0 = expf(b0 - mj), xb1 = expf(b1 - mj);
    float dj = 1.0f / (xb0 + xb1);
    float vj0 = xb0 * dj, vj1 = xb1 * dj;

    #pragma unroll
    for (int it = 0; it < 10; it++) {
        float r0 = e00 + e01 + EPSF, r1 = e10 + e11 + EPSF;
        float c0 = e00 + e10 + EPSF, c1 = e01 + e11 + EPSF;
        float f0 = vi0 / r0, f1 = vi1 / r1;
        e00 *= f0; e01 *= f0; e10 *= f1; e11 *= f1;
        float g0 = vj0 / c0, g1 = vj1 / c1;
        e00 *= g0; e10 *= g0; e01 *= g1; e11 *= g1;
        float iv = 1.0f / (e00 + e01 + e10 + e11 + EPSF);
        e00 *= iv; e01 *= iv; e10 *= iv; e11 *= iv;
    }

    float wm = 0.0f;
    if (i != j) {
        float w = (i > j) ? W[i*N + j] : W[j*N + i];
        wm = 1.0f / (1.0f + expf(-w));
    } else {
        e00 = e01 = e10 = e11 = 0.0f;
    }
    e00 = fminf(fmaxf(e00, 0.0f), 1.0f);
    e01 = fminf(fmaxf(e01, 0.0f), 1.0f);
    e10 = fminf(fmaxf(e10, 0.0f), 1.0f);
    e11 = fminf(fmaxf(e11, 0.0f), 1.0f);

    g_C[0*N2 + p] = wm * e00 / (vi0 * vj0);
    g_C[1*N2 + p] = wm * e01 / (vi0 * vj1);
    g_C[2*N2 + p] = wm * e10 / (vi1 * vj0);
    g_C[3*N2 + p] = wm * e11 / (vi1 * vj1);
}

// ---------------- kernel 2: build + paired-panel LU (rank-64 updates) ----------------
#define SPA_ST 33             // 512 x 33 panel A  (rows rel j0)
#define SPB_ST 33             // 480 x 33 panel B  (rows rel j0+32)
#define SU_ST 264             // 64 x 264 negated-U block (16B-aligned rows)
#define SMEM_LU_BYTES ((N*SPA_ST + 480*SPB_ST + 64*SU_ST) * 4 + N * 4 + 16)

__global__ void __launch_bounds__(NTHR, 1) k_lu(const int* __restrict__ x,
                                                const float* __restrict__ W) {
    extern __shared__ float smem[];
    float* sPA  = smem;                      // [rrel*33 + k], rrel = row - j0
    float* sPB  = sPA + N * SPA_ST;          // [rrel*33 + k], rrel = row - (j0+32)
    float* sU   = sPB + 480 * SPB_ST;        // NEGATED U [k*264 + crel]
    int*   sx   = (int*)(sU + 64 * SU_ST);
    float* sacc = (float*)(sx + N);

    const int batch = blockIdx.x;
    const int tid   = threadIdx.x;
    float* Mb = g_M + (size_t)batch * N2;

    if (batch < BATCH) {
        for (int t = tid; t < N; t += NTHR) sx[t] = x[batch*N + t];
    }
    if (tid == 0) sacc[0] = 0.0f;
    __syncthreads();

    // ---- build padded 512x512 matrix (rows 0..510 <-> nodes 1..511) ----
    {
        int w = tid >> 5, lane = tid & 31;
        for (int r = w; r < N; r += 16) {
            if (r == N - 1) {
                for (int c = lane; c < N; c += 32) Mb[r*N + c] = (c == N-1) ? 1.0f : 0.0f;
                continue;
            }
            int i = r + 1;
            float sum = 0.0f;
            if (batch < BATCH) {
                int xi = sx[i];
                const float* p0 = g_C + (size_t)(xi*2) * N2 + (size_t)i * N;
                const float* p1 = p0 + N2;
                for (int j = lane; j < N; j += 32) {
                    float v0 = p0[j], v1 = p1[j];
                    float v = sx[j] ? v1 : v0;
                    sum += v;
                    int c = j - 1;
                    if (j > 0 && c != r) Mb[r*N + c] = -v;
                }
            } else {
                for (int j = lane; j < N; j += 32) {
                    float v = 0.0f;
                    if (j != i) {
                        float wv = (i > j) ? W[i*N + j] : W[j*N + i];
                        v = 1.0f / (1.0f + expf(-wv));
                    }
                    sum += v;
                    int c = j - 1;
                    if (j > 0 && c != r) Mb[r*N + c] = -v;
                }
            }
            #pragma unroll
            for (int off = 16; off; off >>= 1) sum += __shfl_xor_sync(0xffffffffu, sum, off);
            if (lane == 0) { Mb[r*N + r] = sum; Mb[r*N + (N-1)] = 0.0f; }
        }
    }
    __syncthreads();

    const int tx = tid & 15, ty = tid >> 4;

    for (int pair = 0; pair < NPAIR; pair++) {
        const int j0 = pair * 64, jB = j0 + 32, j1 = j0 + 64;
        const int mA = N - j0;       // panel A rows
        const int mB = N - jB;       // panel B rows

        // ---- load + factor panel A (cols j0..j0+31, rows j0..511) ----
        for (int e = tid; e < mA * 32; e += NTHR) {
            int rr = e >> 5, k = e & 31;
            sPA[rr*SPA_ST + k] = Mb[(size_t)(j0+rr)*N + j0 + k];
        }
        __syncthreads();
        for (int j = 0; j < 32; j++) {
            float pinv = 1.0f / sPA[j*SPA_ST + j];
            int idx = j + 1 + tid;
            if (idx < mA) {
                float l = sPA[idx*SPA_ST + j] * pinv;
                sPA[idx*SPA_ST + j] = l;
                #pragma unroll
                for (int c = j + 1; c < 32; c++)
                    sPA[idx*SPA_ST + c] -= l * sPA[j*SPA_ST + c];
            }
            __syncthreads();
        }

        // ---- U_A for panel-B columns -> sU rows 0..31, cols 0..31 (negated) ----
        if (tid < 32) {
            int c = jB + tid;
            float y[32];
            #pragma unroll
            for (int k = 0; k < 32; k++) y[k] = Mb[(size_t)(j0+k)*N + c];
            #pragma unroll
            for (int k = 1; k < 32; k++) {
                float acc = y[k];
                #pragma unroll
                for (int t = 0; t < k; t++) acc -= sPA[k*SPA_ST + t] * y[t];
                y[k] = acc;
            }
            #pragma unroll
            for (int k = 0; k < 32; k++) sU[k*SU_ST + tid] = -y[k];
        }
        __syncthreads();

        // ---- B strip: load + rank-32 update into sPB (rows jB..511) ----
        {
            int r = tid;
            if (r < mB) {
                const ulonglong2* src =
                    reinterpret_cast<const ulonglong2*>(&Mb[(size_t)(jB+r)*N + jB]);
                u64 acc[16];
                #pragma unroll
                for (int q = 0; q < 8; q++) {
                    ulonglong2 v = src[q];
                    acc[2*q] = v.x; acc[2*q+1] = v.y;
                }
                #pragma unroll 4
                for (int k = 0; k < 32; k++) {
                    u64 a2 = pack_dup(sPA[(r+32)*SPA_ST + k]);
                    const u64* bro = reinterpret_cast<const u64*>(&sU[k*SU_ST]);
                    #pragma unroll
                    for (int q = 0; q < 16; q++)
                        acc[q] = ffma2(a2, bro[q], acc[q]);
                }
                #pragma unroll
                for (int q = 0; q < 16; q++) {
                    float lo, hi; unpack2(acc[q], lo, hi);
                    sPB[r*SPB_ST + 2*q] = lo;
                    sPB[r*SPB_ST + 2*q + 1] = hi;
                }
            }
        }
        __syncthreads();

        // ---- factor panel B in sPB ----
        for (int j = 0; j < 32; j++) {
            float pinv = 1.0f / sPB[j*SPB_ST + j];
            int idx = j + 1 + tid;
            if (idx < mB) {
                float l = sPB[idx*SPB_ST + j] * pinv;
                sPB[idx*SPB_ST + j] = l;
                #pragma unroll
                for (int c = j + 1; c < 32; c++)
                    sPB[idx*SPB_ST + c] -= l * sPB[j*SPB_ST + c];
            }
            __syncthreads();
        }

        // ---- logdet from the 64 pivots ----
        if (tid < 32) {
            float v = logf(fabsf(sPA[tid*SPA_ST + tid]))
                    + logf(fabsf(sPB[tid*SPB_ST + tid]));
            #pragma unroll
            for (int off = 16; off; off >>= 1) v += __shfl_xor_sync(0xffffffffu, v, off);
            if (tid == 0) sacc[0] += v;
        }

        // ---- trailing: rank-64 update, 256-col chunks ----
        for (int cb = j1; cb < N; cb += 256) {
            int cw = min(256, N - cb);          // multiple of 64

            // two-stage trisolve, y[32] live per stage (no spills)
            if (tid < cw) {
                int c = cb + tid;
                // stage 1: solve with panel A (rows j0..j0+31)
                float y[32];
                #pragma unroll
                for (int k = 0; k < 32; k++) y[k] = Mb[(size_t)(j0+k)*N + c];
                #pragma unroll
                for (int k = 1; k < 32; k++) {
                    float acc = y[k];
                    #pragma unroll
                    for (int t = 0; t < k; t++) acc -= sPA[k*SPA_ST + t] * y[t];
                    y[k] = acc;
                }
                #pragma unroll
                for (int k = 0; k < 32; k++) sU[k*SU_ST + tid] = -y[k];

                // stage 2: pre-update rows jB..j1-1 using stage-1 registers,
                // then solve with panel B
                float y2[32];
                #pragma unroll
                for (int i = 0; i < 32; i++) y2[i] = Mb[(size_t)(jB+i)*N + c];
                #pragma unroll 4
                for (int k = 0; k < 32; k++) {
                    float u = y[k];
                    #pragma unroll
                    for (int i = 0; i < 32; i++)
                        y2[i] -= sPA[(32+i)*SPA_ST + k] * u;
                }
                #pragma unroll
                for (int k = 1; k < 32; k++) {
                    float acc = y2[k];
                    #pragma unroll
                    for (int t = 0; t < k; t++) acc -= sPB[k*SPB_ST + t] * y2[t];
                    y2[k] = acc;
                }
                #pragma unroll
                for (int k = 0; k < 32; k++) sU[(32+k)*SU_ST + tid] = -y2[k];
            }
            __syncthreads();

            // GEMM: A22 += L * (-U); 8 rows x (4+4) cols per thread,
            // accumulators initialized from global (prefetch before k-loop)
            for (int cc = 0; cc < cw; cc += 128) {
                const bool gb = (cc + 128 <= cw);       // second 64-col group valid?
                const int c0a = cb + cc + tx*4;
                const int c0b = c0a + 64;
                for (int rb = j1; rb < N; rb += 256) {
                    bool rok[8]; int rpA[8], rpB[8], rg[8];
                    #pragma unroll
                    for (int ii = 0; ii < 8; ii++) {
                        int r = rb + ty + 32*ii;
                        rok[ii] = (r < N);
                        rg[ii]  = rok[ii] ? r : (N-1);
                        rpA[ii] = rg[ii] - j0;
                        rpB[ii] = rg[ii] - jB;
                    }
                    u64 acc[8][4];
                    #pragma unroll
                    for (int ii = 0; ii < 8; ii++) {
                        ulonglong2 va = *reinterpret_cast<const ulonglong2*>(
                            &Mb[(size_t)rg[ii]*N + c0a]);
                        acc[ii][0] = va.x; acc[ii][1] = va.y;
                        if (gb) {
                            ulonglong2 vb = *reinterpret_cast<const ulonglong2*>(
                                &Mb[(size_t)rg[ii]*N + c0b]);
                            acc[ii][2] = vb.x; acc[ii][3] = vb.y;
                        } else {
                            acc[ii][2] = 0; acc[ii][3] = 0;
                        }
                    }

                    #pragma unroll 8
                    for (int k = 0; k < 32; k++) {
                        ulonglong2 bA = *reinterpret_cast<const ulonglong2*>(
                            &sU[k*SU_ST + cc + tx*4]);
                        ulonglong2 bB = *reinterpret_cast<const ulonglong2*>(
                            &sU[k*SU_ST + cc + 64 + tx*4]);
                        #pragma unroll
                        for (int ii = 0; ii < 8; ii++) {
                            u64 a2 = pack_dup(sPA[rpA[ii]*SPA_ST + k]);
                            acc[ii][0] = ffma2(a2, bA.x, acc[ii][0]);
                            acc[ii][1] = ffma2(a2, bA.y, acc[ii][1]);
                            acc[ii][2] = ffma2(a2, bB.x, acc[ii][2]);
                            acc[ii][3] = ffma2(a2, bB.y, acc[ii][3]);
                        }
                    }
                    #pragma unroll 8
                    for (int k = 32; k < 64; k++) {
                        ulonglong2 bA = *reinterpret_cast<const ulonglong2*>(
                            &sU[k*SU_ST + cc + tx*4]);
                        ulonglong2 bB = *reinterpret_cast<const ulonglong2*>(
                            &sU[k*SU_ST + cc + 64 + tx*4]);
                        #pragma unroll
                        for (int ii = 0; ii < 8; ii++) {
                            u64 a2 = pack_dup(sPB[rpB[ii]*SPB_ST + (k-32)]);
                            acc[ii][0] = ffma2(a2, bA.x, acc[ii][0]);
                            acc[ii][1] = ffma2(a2, bA.y, acc[ii][1]);
                            acc[ii][2] = ffma2(a2, bB.x, acc[ii][2]);
                            acc[ii][3] = ffma2(a2, bB.y, acc[ii][3]);
                        }
                    }
                    // store epilogue
                    #pragma unroll
                    for (int ii = 0; ii < 8; ii++) {
                        if (rok[ii]) {
                            ulonglong2 oa; oa.x = acc[ii][0]; oa.y = acc[ii][1];
                            *reinterpret_cast<ulonglong2*>(&Mb[(size_t)rg[ii]*N + c0a]) = oa;
                            if (gb) {
                                ulonglong2 ob; ob.x = acc[ii][2]; ob.y = acc[ii][3];
                                *reinterpret_cast<ulonglong2*>(&Mb[(size_t)rg[ii]*N + c0b]) = ob;
                            }
                        }
                    }
                }
            }
            __syncthreads();
        }
    }
    __syncthreads();
    if (tid == 0) g_logdet[batch] = sacc[0];
}

// ---------------- kernel 3: combine ----------------
__global__ void k_final(const int* __restrict__ x, const float* __restrict__ Vc,
                        float* __restrict__ out) {
    __shared__ float red[256];
    int b = blockIdx.x, tid = threadIdx.x;
    float s = 0.0f;
    for (int i = tid; i < N; i += 256) {
        int xi = x[b*N + i];
        float a0 = Vc[2*i], a1 = Vc[2*i+1];
        float m = fmaxf(a0, a1);
        float lse = m + logf(expf(a0 - m) + expf(a1 - m));
        s += (xi ? a1 : a0) - lse;
    }
    red[tid] = s;
    __syncthreads();
    #pragma unroll
    for (int o = 128; o; o >>= 1) {
        if (tid < o) red[tid] += red[tid + o];
        __syncthreads();
    }
    if (tid == 0) out[b] = red[0] + g_logdet[b] - g_logdet[BATCH];
}

// ---------------- launcher ----------------
extern "C" void kernel_launch(void* const* d_in, const int* in_sizes, int n_in,
                              void* d_out, int out_size) {
    const int* x = nullptr;
    const float* W = nullptr;
    const float* Vc = nullptr;
    const float* Ec = nullptr;
    for (int k = 0; k < n_in; k++) {
        switch (in_sizes[k]) {
            case BATCH * N:   x  = (const int*)d_in[k];   break;  // 65536
            case N * N:       W  = (const float*)d_in[k]; break;  // 262144
            case N * 2:       Vc = (const float*)d_in[k]; break;  // 1024
            case N * N * 4:   Ec = (const float*)d_in[k]; break;  // 1048576
        }
    }
    float* out = (float*)d_out;

    cudaFuncSetAttribute(k_lu, cudaFuncAttributeMaxDynamicSharedMemorySize, SMEM_LU_BYTES);

    k_ipf<<<N2 / 256, 256>>>(W, Vc, Ec);
    k_lu<<<NMAT, NTHR, SMEM_LU_BYTES>>>(x, W);
    k_final<<<BATCH, 256>>>(x, Vc, out);
}

// round 6
// speedup vs baseline: 1.1598x; 1.0663x over previous
#include <cuda_runtime.h>
#include <math.h>
#include <stdint.h>

#define N 512
#define N2 (N*N)
#define BATCH 128
#define NMAT 129           // 128 batch matrices + 1 for L0
#define EPSF 1e-7f
#define NTHR 512
#define NPAN 16            // 16 panels of width 32

typedef unsigned long long u64;

// packed f32x2 FMA (Blackwell FFMA2 — only reachable via PTX)
__device__ __forceinline__ u64 ffma2(u64 a, u64 b, u64 c) {
    u64 d;
    asm("fma.rn.f32x2 %0, %1, %2, %3;" : "=l"(d) : "l"(a), "l"(b), "l"(c));
    return d;
}
__device__ __forceinline__ u64 pack_dup(float a) {
    u64 d; unsigned int u = __float_as_uint(a);
    asm("mov.b64 %0, {%1, %1};" : "=l"(d) : "r"(u));
    return d;
}

// ---------------- device scratch (no allocations allowed) ----------------
__device__ float g_C[4 * N2];                                   // 4 planes, 4 MB
__device__ __align__(16) float g_M[(size_t)NMAT * N2 + 64];     // 129 matrices
__device__ float g_logdet[NMAT];

// ---------------- kernel 1: IPF + plane construction ----------------
__global__ void k_ipf(const float* __restrict__ W, const float* __restrict__ Vc,
                      const float* __restrict__ Ec) {
    int p = blockIdx.x * blockDim.x + threadIdx.x;
    int i = p >> 9;
    int j = p & (N - 1);

    float4 e4 = reinterpret_cast<const float4*>(Ec)[p];
    float e00 = expf(e4.x), e01 = expf(e4.y), e10 = expf(e4.z), e11 = expf(e4.w);
    float inv = 1.0f / (e00 + e01 + e10 + e11);
    e00 *= inv; e01 *= inv; e10 *= inv; e11 *= inv;

    float a0 = Vc[2*i], a1 = Vc[2*i+1];
    float mi = fmaxf(a0, a1);
    float xa0 = expf(a0 - mi), xa1 = expf(a1 - mi);
    float di = 1.0f / (xa0 + xa1);
    float vi0 = xa0 * di, vi1 = xa1 * di;

    float b0 = Vc[2*j], b1 = Vc[2*j+1];
    float mj = fmaxf(b0, b1);
    float xb0 = expf(b0 - mj), xb1 = expf(b1 - mj);
    float dj = 1.0f / (xb0 + xb1);
    float vj0 = xb0 * dj, vj1 = xb1 * dj;

    #pragma unroll
    for (int it = 0; it < 10; it++) {
        float r0 = e00 + e01 + EPSF, r1 = e10 + e11 + EPSF;
        float c0 = e00 + e10 + EPSF, c1 = e01 + e11 + EPSF;
        float f0 = vi0 / r0, f1 = vi1 / r1;
        e00 *= f0; e01 *= f0; e10 *= f1; e11 *= f1;
        float g0 = vj0 / c0, g1 = vj1 / c1;
        e00 *= g0; e10 *= g0; e01 *= g1; e11 *= g1;
        float iv = 1.0f / (e00 + e01 + e10 + e11 + EPSF);
        e00 *= iv; e01 *= iv; e10 *= iv; e11 *= iv;
    }

    float wm = 0.0f;
    if (i != j) {
        float w = (i > j) ? W[i*N + j] : W[j*N + i];
        wm = 1.0f / (1.0f + expf(-w));
    } else {
        e00 = e01 = e10 = e11 = 0.0f;
    }
    e00 = fminf(fmaxf(e00, 0.0f), 1.0f);
    e01 = fminf(fmaxf(e01, 0.0f), 1.0f);
    e10 = fminf(fmaxf(e10, 0.0f), 1.0f);
    e11 = fminf(fmaxf(e11, 0.0f), 1.0f);

    g_C[0*N2 + p] = wm * e00 / (vi0 * vj0);
    g_C[1*N2 + p] = wm * e01 / (vi0 * vj1);
    g_C[2*N2 + p] = wm * e10 / (vi1 * vj0);
    g_C[3*N2 + p] = wm * e11 / (vi1 * vj1);
}

// ---------------- kernel 2: build + blocked LU (NB=32, barrier-light) ----------------
#define STD 484            // sPTd row stride in u64 units (484*8B, 16B multiple)
#define SU_ST 264          // sU row stride in floats (16B multiple)
#define SMEM_LU_BYTES (32*STD*8 + 32*33*4 + 32*4 + 32*SU_ST*4 + N*4 + 16)

__global__ void __launch_bounds__(NTHR, 1) k_lu(const int* __restrict__ x,
                                                const float* __restrict__ W) {
    extern __shared__ char smraw[];
    u64*   sPTd  = (u64*)smraw;                 // [k][rrel] duplicated -L21, 124KB
    float* sD    = (float*)(sPTd + 32*STD);     // 32x33 L11\U11 block
    float* sDinv = sD + 32*33;                  // 1/diag
    float* sU    = sDinv + 32;                  // negated U12 [k][c-cb]
    int*   sx    = (int*)(sU + 32*SU_ST);

    const int batch = blockIdx.x;
    const int tid   = threadIdx.x;
    float* Mb = g_M + (size_t)batch * N2;

    if (batch < BATCH) {
        for (int t = tid; t < N; t += NTHR) sx[t] = x[batch*N + t];
    }
    __syncthreads();

    // ---- build padded 512x512 matrix (rows 0..510 <-> nodes 1..511) ----
    {
        int w = tid >> 5, lane = tid & 31;
        for (int r = w; r < N; r += 16) {
            if (r == N - 1) {
                for (int c = lane; c < N; c += 32) Mb[r*N + c] = (c == N-1) ? 1.0f : 0.0f;
                continue;
            }
            int i = r + 1;
            float sum = 0.0f;
            if (batch < BATCH) {
                int xi = sx[i];
                const float* p0 = g_C + (size_t)(xi*2) * N2 + (size_t)i * N;
                const float* p1 = p0 + N2;
                for (int j = lane; j < N; j += 32) {
                    float v0 = p0[j], v1 = p1[j];
                    float v = sx[j] ? v1 : v0;
                    sum += v;
                    int c = j - 1;
                    if (j > 0 && c != r) Mb[r*N + c] = -v;
                }
            } else {
                for (int j = lane; j < N; j += 32) {
                    float v = 0.0f;
                    if (j != i) {
                        float wv = (i > j) ? W[i*N + j] : W[j*N + i];
                        v = 1.0f / (1.0f + expf(-wv));
                    }
                    sum += v;
                    int c = j - 1;
                    if (j > 0 && c != r) Mb[r*N + c] = -v;
                }
            }
            #pragma unroll
            for (int off = 16; off; off >>= 1) sum += __shfl_xor_sync(0xffffffffu, sum, off);
            if (lane == 0) { Mb[r*N + r] = sum; Mb[r*N + (N-1)] = 0.0f; }
        }
    }
    __syncthreads();

    const int tx = tid & 15, ty = tid >> 4;
    float ld_local = 0.0f;          // per-lane logdet (warp 0 only)

    for (int kb = 0; kb < NPAN; kb++) {
        const int j0 = kb * 32, j1 = j0 + 32;

        // ---- warp 0: factor 32x32 diagonal block in registers (no CTA barriers) ----
        if (tid < 32) {
            const int lane = tid;
            float v[32];
            const float4* rp = reinterpret_cast<const float4*>(&Mb[(size_t)(j0+lane)*N + j0]);
            #pragma unroll
            for (int q = 0; q < 8; q++) {
                float4 t4 = rp[q];
                v[4*q]=t4.x; v[4*q+1]=t4.y; v[4*q+2]=t4.z; v[4*q+3]=t4.w;
            }
            #pragma unroll
            for (int j = 0; j < 32; j++) {
                float diag = __shfl_sync(0xffffffffu, v[j], j);
                float l = v[j] * (1.0f / diag);
                #pragma unroll
                for (int c = j + 1; c < 32; c++) {
                    float ujc = __shfl_sync(0xffffffffu, v[c], j);
                    if (lane > j) v[c] -= l * ujc;
                }
                if (lane > j) v[j] = l;     // unit-diag L below, U on/above
            }
            ld_local += logf(fabsf(v[lane]));
            #pragma unroll
            for (int c = 0; c < 32; c++) sD[lane*33 + c] = v[c];
            sDinv[lane] = 1.0f / v[lane];
        }
        __syncthreads();

        // ---- all threads: L21 rows via register back-substitution (no barriers) ----
        {
            int r = j1 + tid;
            if (r < N) {
                float a[32];
                const float4* rp = reinterpret_cast<const float4*>(&Mb[(size_t)r*N + j0]);
                #pragma unroll
                for (int q = 0; q < 8; q++) {
                    float4 t4 = rp[q];
                    a[4*q]=t4.x; a[4*q+1]=t4.y; a[4*q+2]=t4.z; a[4*q+3]=t4.w;
                }
                #pragma unroll
                for (int k = 0; k < 32; k++) {
                    float acc = a[k];
                    #pragma unroll
                    for (int t = 0; t < k; t++) acc -= a[t] * sD[t*33 + k];
                    a[k] = acc * sDinv[k];
                }
                int rrel = r - j1;
                #pragma unroll
                for (int k = 0; k < 32; k++)
                    sPTd[k*STD + rrel] = pack_dup(-a[k]);
            }
        }
        __syncthreads();

        // ---- trailing update in 256-col chunks ----
        for (int cb = j1; cb < N; cb += 256) {
            const int cw = min(256, N - cb);

            // trisolve: sU = -(L11^{-1} A12), one thread per column
            if (tid < cw) {
                int c = cb + tid;
                float y[32];
                #pragma unroll
                for (int k = 0; k < 32; k++) y[k] = Mb[(size_t)(j0+k)*N + c];
                #pragma unroll
                for (int k = 1; k < 32; k++) {
                    float acc = y[k];
                    #pragma unroll
                    for (int t = 0; t < k; t++) acc -= sD[k*33 + t] * y[t];
                    y[k] = acc;
                }
                #pragma unroll
                for (int k = 0; k < 32; k++) sU[k*SU_ST + tid] = -y[k];
            }
            __syncthreads();

            // GEMM: A22 += L21 * (-U12); 8x8 per thread, dup-a from sPTd (no movs)
            for (int cc = 0; cc < cw; cc += 128) {
                if (cc + tx*8 < cw) {
                    const int c0 = cb + cc + tx*8;
                    for (int rb = j1; rb < N; rb += 256) {
                        const int r0 = rb + ty*8;
                        if (r0 < N) {
                            const int rrel0 = r0 - j1;
                            u64 acc[8][4];
                            #pragma unroll
                            for (int ii = 0; ii < 8; ii++) {
                                const ulonglong2* src = reinterpret_cast<const ulonglong2*>(
                                    &Mb[(size_t)(r0+ii)*N + c0]);
                                ulonglong2 u0 = src[0], u1 = src[1];
                                acc[ii][0]=u0.x; acc[ii][1]=u0.y;
                                acc[ii][2]=u1.x; acc[ii][3]=u1.y;
                            }
                            #pragma unroll 8
                            for (int k = 0; k < 32; k++) {
                                const ulonglong2* ap = reinterpret_cast<const ulonglong2*>(
                                    &sPTd[k*STD + rrel0]);
                                ulonglong2 a01 = ap[0], a23 = ap[1], a45 = ap[2], a67 = ap[3];
                                const ulonglong2* bp = reinterpret_cast<const ulonglong2*>(
                                    &sU[k*SU_ST + cc + tx*8]);
                                ulonglong2 b0 = bp[0], b1 = bp[1];
                                acc[0][0]=ffma2(a01.x,b0.x,acc[0][0]);
                                acc[0][1]=ffma2(a01.x,b0.y,acc[0][1]);
                                acc[0][2]=ffma2(a01.x,b1.x,acc[0][2]);
                                acc[0][3]=ffma2(a01.x,b1.y,acc[0][3]);
                                acc[1][0]=ffma2(a01.y,b0.x,acc[1][0]);
                                acc[1][1]=ffma2(a01.y,b0.y,acc[1][1]);
                                acc[1][2]=ffma2(a01.y,b1.x,acc[1][2]);
                                acc[1][3]=ffma2(a01.y,b1.y,acc[1][3]);
                                acc[2][0]=ffma2(a23.x,b0.x,acc[2][0]);
                                acc[2][1]=ffma2(a23.x,b0.y,acc[2][1]);
                                acc[2][2]=ffma2(a23.x,b1.x,acc[2][2]);
                                acc[2][3]=ffma2(a23.x,b1.y,acc[2][3]);
                                acc[3][0]=ffma2(a23.y,b0.x,acc[3][0]);
                                acc[3][1]=ffma2(a23.y,b0.y,acc[3][1]);
                                acc[3][2]=ffma2(a23.y,b1.x,acc[3][2]);
                                acc[3][3]=ffma2(a23.y,b1.y,acc[3][3]);
                                acc[4][0]=ffma2(a45.x,b0.x,acc[4][0]);
                                acc[4][1]=ffma2(a45.x,b0.y,acc[4][1]);
                                acc[4][2]=ffma2(a45.x,b1.x,acc[4][2]);
                                acc[4][3]=ffma2(a45.x,b1.y,acc[4][3]);
                                acc[5][0]=ffma2(a45.y,b0.x,acc[5][0]);
                                acc[5][1]=ffma2(a45.y,b0.y,acc[5][1]);
                                acc[5][2]=ffma2(a45.y,b1.x,acc[5][2]);
                                acc[5][3]=ffma2(a45.y,b1.y,acc[5][3]);
                                acc[6][0]=ffma2(a67.x,b0.x,acc[6][0]);
                                acc[6][1]=ffma2(a67.x,b0.y,acc[6][1]);
                                acc[6][2]=ffma2(a67.x,b1.x,acc[6][2]);
                                acc[6][3]=ffma2(a67.x,b1.y,acc[6][3]);
                                acc[7][0]=ffma2(a67.y,b0.x,acc[7][0]);
                                acc[7][1]=ffma2(a67.y,b0.y,acc[7][1]);
                                acc[7][2]=ffma2(a67.y,b1.x,acc[7][2]);
                                acc[7][3]=ffma2(a67.y,b1.y,acc[7][3]);
                            }
                            #pragma unroll
                            for (int ii = 0; ii < 8; ii++) {
                                ulonglong2* dst = reinterpret_cast<ulonglong2*>(
                                    &Mb[(size_t)(r0+ii)*N + c0]);
                                ulonglong2 o0, o1;
                                o0.x = acc[ii][0]; o0.y = acc[ii][1];
                                o1.x = acc[ii][2]; o1.y = acc[ii][3];
                                dst[0] = o0; dst[1] = o1;
                            }
                        }
                    }
                }
            }
            __syncthreads();
        }
    }

    // ---- logdet reduce (all 512 pivots accumulated in warp 0 lanes) ----
    if (tid < 32) {
        float v = ld_local;
        #pragma unroll
        for (int off = 16; off; off >>= 1) v += __shfl_xor_sync(0xffffffffu, v, off);
        if (tid == 0) g_logdet[batch] = v;
    }
}

// ---------------- kernel 3: combine ----------------
__global__ void k_final(const int* __restrict__ x, const float* __restrict__ Vc,
                        float* __restrict__ out) {
    __shared__ float red[256];
    int b = blockIdx.x, tid = threadIdx.x;
    float s = 0.0f;
    for (int i = tid; i < N; i += 256) {
        int xi = x[b*N + i];
        float a0 = Vc[2*i], a1 = Vc[2*i+1];
        float m = fmaxf(a0, a1);
        float lse = m + logf(expf(a0 - m) + expf(a1 - m));
        s += (xi ? a1 : a0) - lse;
    }
    red[tid] = s;
    __syncthreads();
    #pragma unroll
    for (int o = 128; o; o >>= 1) {
        if (tid < o) red[tid] += red[tid + o];
        __syncthreads();
    }
    if (tid == 0) out[b] = red[0] + g_logdet[b] - g_logdet[BATCH];
}

// ---------------- launcher ----------------
extern "C" void kernel_launch(void* const* d_in, const int* in_sizes, int n_in,
                              void* d_out, int out_size) {
    const int* x = nullptr;
    const float* W = nullptr;
    const float* Vc = nullptr;
    const float* Ec = nullptr;
    for (int k = 0; k < n_in; k++) {
        switch (in_sizes[k]) {
            case BATCH * N:   x  = (const int*)d_in[k];   break;  // 65536
            case N * N:       W  = (const float*)d_in[k]; break;  // 262144
            case N * 2:       Vc = (const float*)d_in[k]; break;  // 1024
            case N * N * 4:   Ec = (const float*)d_in[k]; break;  // 1048576
        }
    }
    float* out = (float*)d_out;

    cudaFuncSetAttribute(k_lu, cudaFuncAttributeMaxDynamicSharedMemorySize, SMEM_LU_BYTES);

    k_ipf<<<N2 / 256, 256>>>(W, Vc, Ec);
    k_lu<<<NMAT, NTHR, SMEM_LU_BYTES>>>(x, W);
    k_final<<<BATCH, 256>>>(x, Vc, out);
}